// round 5
// baseline (speedup 1.0000x reference)
#include <cuda_runtime.h>
#include <cstdint>

// minGRU bidirectional scan. R5: split-chunk float4 everywhere, 3-stage TMA
// input ring, direct coalesced STG output, early prefetch.
// x: [B, 512, L] fp32 -> out: [B, 256, L] fp32.
//   out channel c2 (0..255): rev = c2>=128, c = c2&127
//   h row = x[b, (rev?256:0)+c, :], gate row = h row + 128 channels.
// Recurrence (logical order; rev scans t = L-1..0):
//   out_t = a_t*out_{t-1} + b_t,  a = 1/(1+e^gate), b = (1-a)*g(h),
//   g(v) = v>=0 ? 1+v : e^v.
//
// Thread t owns logical chunks LO=[4t,4t+4) and HI=[L/2+4t, L/2+4t+4):
// stride-16B lane access -> conflict-free LDS.128 / fully-coalesced STG.128.
// Block scan runs two interleaved (A,B) affine scans (lo/hi half-sequences);
// hi carries are seeded with the lo-half total state.

constexpr int L      = 8192;
constexpr int NT     = 1024;
constexpr int NW     = NT / 32;
constexpr int STAGES = 3;

// smem: 3 stages x {h[L], g[L]} floats, then mbar[3], scan arrays, sMid
constexpr int SMEM_FLOATS = STAGES * 2 * L;
constexpr int SMEM_BYTES  = SMEM_FLOATS * 4 + STAGES * 8 + (4 * NW + 2) * 4;

__device__ __forceinline__ float fast_rcp(float v) {
    float r;
    asm("rcp.approx.f32 %0, %1;" : "=f"(r) : "f"(v));
    return r;
}

__device__ __forceinline__ float4 rev4(float4 v) {
    return make_float4(v.w, v.z, v.y, v.x);
}

__device__ __forceinline__ void mbar_wait(uint32_t mbar, uint32_t parity) {
    uint32_t done;
    asm volatile(
        "{\n\t.reg .pred p;\n\t"
        "mbarrier.try_wait.parity.shared::cta.b64 p, [%1], %2;\n\t"
        "selp.b32 %0, 1, 0, p;\n\t}"
        : "=r"(done) : "r"(mbar), "r"(parity) : "memory");
    while (!done) {
        asm volatile(
            "{\n\t.reg .pred p;\n\t"
            "mbarrier.try_wait.parity.shared::cta.b64 p, [%1], %2, 0x989680;\n\t"
            "selp.b32 %0, 1, 0, p;\n\t}"
            : "=r"(done) : "r"(mbar), "r"(parity) : "memory");
    }
}

__device__ __forceinline__ void bulk_load_seq(const float* __restrict__ x,
                                              int seq, uint32_t hdst, uint32_t gdst,
                                              uint32_t mbar) {
    const int b   = seq >> 8;
    const int c2  = seq & 255;
    const int hch = ((c2 & 128) ? 256 : 0) + (c2 & 127);
    const float* hrow = x + (size_t)(b * 512 + hch) * L;
    const float* grow = hrow + (size_t)128 * L;
    asm volatile("mbarrier.arrive.expect_tx.shared.b64 _, [%0], %1;"
                 :: "r"(mbar), "r"(2 * L * 4) : "memory");
    asm volatile("cp.async.bulk.shared::cta.global.mbarrier::complete_tx::bytes "
                 "[%0], [%1], %2, [%3];"
                 :: "r"(hdst), "l"(hrow), "r"(L * 4), "r"(mbar) : "memory");
    asm volatile("cp.async.bulk.shared::cta.global.mbarrier::complete_tx::bytes "
                 "[%0], [%1], %2, [%3];"
                 :: "r"(gdst), "l"(grow), "r"(L * 4), "r"(mbar) : "memory");
}

__global__ __launch_bounds__(NT, 1)
void mingru_bidir_kernel(const float* __restrict__ x, float* __restrict__ out,
                         int nseq) {
    extern __shared__ float smem[];
    uint64_t* mb = (uint64_t*)(smem + SMEM_FLOATS);
    float* sAlo = (float*)(mb + STAGES);
    float* sBlo = sAlo + NW;
    float* sAhi = sBlo + NW;
    float* sBhi = sAhi + NW;
    float* sMid = sBhi + NW;

    const int tid  = threadIdx.x;
    const int lane = tid & 31;
    const int warp = tid >> 5;
    const int G    = gridDim.x;

    const uint32_t smem_u32 = (uint32_t)__cvta_generic_to_shared(smem);
    const uint32_t mbar_u32 = (uint32_t)__cvta_generic_to_shared(mb);

    const int n = (nseq - blockIdx.x + G - 1) / G;

    if (tid == 0) {
        #pragma unroll
        for (int s = 0; s < STAGES; ++s)
            asm volatile("mbarrier.init.shared.b64 [%0], 1;"
                         :: "r"(mbar_u32 + 8 * s) : "memory");
        #pragma unroll
        for (int s = 0; s < STAGES; ++s)
            if (s < n)
                bulk_load_seq(x, blockIdx.x + s * G,
                              smem_u32 + (s * 2) * L * 4,
                              smem_u32 + (s * 2 + 1) * L * 4,
                              mbar_u32 + 8 * s);
    }
    __syncthreads();

    for (int i = 0; i < n; ++i) {
        const int st  = i % STAGES;
        const int seq = blockIdx.x + i * G;
        const float4* h4 = (const float4*)(smem + st * 2 * L);
        const float4* g4 = (const float4*)(smem + st * 2 * L + L);

        mbar_wait(mbar_u32 + 8 * st, (uint32_t)((i / STAGES) & 1));

        const bool rev = (seq & 128) != 0;

        // ---- Phase 1: conflict-free vector loads (logical chunk order) ----
        float4 hq0, hq1, gq0, gq1;
        if (!rev) {
            hq0 = h4[tid];          hq1 = h4[L / 8 + tid];
            gq0 = g4[tid];          gq1 = g4[L / 8 + tid];
        } else {
            hq0 = rev4(h4[L / 4 - 1 - tid]);  hq1 = rev4(h4[L / 8 - 1 - tid]);
            gq0 = rev4(g4[L / 4 - 1 - tid]);  gq1 = rev4(g4[L / 8 - 1 - tid]);
        }
        const float hv[8] = {hq0.x, hq0.y, hq0.z, hq0.w, hq1.x, hq1.y, hq1.z, hq1.w};
        const float gv[8] = {gq0.x, gq0.y, gq0.z, gq0.w, gq1.x, gq1.y, gq1.z, gq1.w};

        float av[8], bv[8];
        float A0 = 1.0f, B0 = 0.0f, A1 = 1.0f, B1 = 0.0f;
        #pragma unroll
        for (int j = 0; j < 8; ++j) {
            const float a  = fast_rcp(1.0f + __expf(gv[j]));
            const float gh = (hv[j] >= 0.0f) ? (1.0f + hv[j]) : __expf(hv[j]);
            const float bb = (1.0f - a) * gh;
            av[j] = a;
            bv[j] = bb;
            if (j < 4) { B0 = fmaf(B0, a, bb); A0 *= a; }
            else       { B1 = fmaf(B1, a, bb); A1 *= a; }
        }

        // ---- Phase 2: two interleaved warp scans (lo / hi half-sequence) ----
        float Al = A0, Bl = B0, Ah = A1, Bh = B1;
        #pragma unroll
        for (int off = 1; off < 32; off <<= 1) {
            const float Alu = __shfl_up_sync(0xFFFFFFFFu, Al, off);
            const float Blu = __shfl_up_sync(0xFFFFFFFFu, Bl, off);
            const float Ahu = __shfl_up_sync(0xFFFFFFFFu, Ah, off);
            const float Bhu = __shfl_up_sync(0xFFFFFFFFu, Bh, off);
            if (lane >= off) {
                Bl = fmaf(Blu, Al, Bl);  Al = Alu * Al;
                Bh = fmaf(Bhu, Ah, Bh);  Ah = Ahu * Ah;
            }
        }
        float Ael = __shfl_up_sync(0xFFFFFFFFu, Al, 1);
        float Bel = __shfl_up_sync(0xFFFFFFFFu, Bl, 1);
        float Aeh = __shfl_up_sync(0xFFFFFFFFu, Ah, 1);
        float Beh = __shfl_up_sync(0xFFFFFFFFu, Bh, 1);
        if (lane == 0) { Ael = 1.0f; Bel = 0.0f; Aeh = 1.0f; Beh = 0.0f; }

        if (lane == 31) {
            sAlo[warp] = Al; sBlo[warp] = Bl;
            sAhi[warp] = Ah; sBhi[warp] = Bh;
        }
        __syncthreads();   // stage st fully read; scan inputs visible

        // Early prefetch of seq i+STAGES into the freed stage
        if (tid == 0 && i + STAGES < n)
            bulk_load_seq(x, seq + STAGES * G,
                          smem_u32 + (st * 2) * L * 4,
                          smem_u32 + (st * 2 + 1) * L * 4,
                          mbar_u32 + 8 * st);

        if (warp == 0) {
            float wal = sAlo[lane], wbl = sBlo[lane];
            float wah = sAhi[lane], wbh = sBhi[lane];
            #pragma unroll
            for (int off = 1; off < NW; off <<= 1) {
                const float Alu = __shfl_up_sync(0xFFFFFFFFu, wal, off);
                const float Blu = __shfl_up_sync(0xFFFFFFFFu, wbl, off);
                const float Ahu = __shfl_up_sync(0xFFFFFFFFu, wah, off);
                const float Bhu = __shfl_up_sync(0xFFFFFFFFu, wbh, off);
                if (lane >= off) {
                    wbl = fmaf(Blu, wal, wbl);  wal = Alu * wal;
                    wbh = fmaf(Bhu, wah, wbh);  wah = Ahu * wah;
                }
            }
            const float wael = __shfl_up_sync(0xFFFFFFFFu, wal, 1);
            const float wbel = __shfl_up_sync(0xFFFFFFFFu, wbl, 1);
            const float waeh = __shfl_up_sync(0xFFFFFFFFu, wah, 1);
            const float wbeh = __shfl_up_sync(0xFFFFFFFFu, wbh, 1);
            if (lane == 31) *sMid = wbl;   // lo-half total applied to 0
            sAlo[lane] = (lane == 0) ? 1.0f : wael;
            sBlo[lane] = (lane == 0) ? 0.0f : wbel;
            sAhi[lane] = (lane == 0) ? 1.0f : waeh;
            sBhi[lane] = (lane == 0) ? 0.0f : wbeh;
        }
        __syncthreads();

        // carries: lo starts from 0; hi starts from lo-half total state (sMid)
        const float smid     = *sMid;
        const float carry_lo = fmaf(sBlo[warp], Ael, Bel);
        const float st_hi_w  = fmaf(sAhi[warp], smid, sBhi[warp]);
        const float carry_hi = fmaf(Aeh, st_hi_w, Beh);

        // ---- Phase 3: two independent replays + coalesced STG.128 ----
        float o[8];
        float s0 = carry_lo, s1 = carry_hi;
        #pragma unroll
        for (int j = 0; j < 4; ++j) { s0 = fmaf(av[j], s0, bv[j]);     o[j]     = s0; }
        #pragma unroll
        for (int j = 0; j < 4; ++j) { s1 = fmaf(av[4 + j], s1, bv[4 + j]); o[4 + j] = s1; }

        float4* o4 = (float4*)(out + (size_t)((seq >> 8) * 256 + (seq & 255)) * L);
        if (!rev) {
            o4[tid]         = make_float4(o[0], o[1], o[2], o[3]);
            o4[L / 8 + tid] = make_float4(o[4], o[5], o[6], o[7]);
        } else {
            o4[L / 4 - 1 - tid] = make_float4(o[3], o[2], o[1], o[0]);
            o4[L / 8 - 1 - tid] = make_float4(o[7], o[6], o[5], o[4]);
        }
    }
}

extern "C" void kernel_launch(void* const* d_in, const int* in_sizes, int n_in,
                              void* d_out, int out_size) {
    const float* x = (const float*)d_in[0];
    float* out = (float*)d_out;
    const int B = in_sizes[0] / (512 * L);
    const int nseq = B * 256;

    int dev = 0, nsm = 148;
    cudaGetDevice(&dev);
    cudaDeviceGetAttribute(&nsm, cudaDevAttrMultiProcessorCount, dev);
    const int G = nsm < nseq ? nsm : nseq;

    cudaFuncSetAttribute(mingru_bidir_kernel,
                         cudaFuncAttributeMaxDynamicSharedMemorySize, SMEM_BYTES);
    mingru_bidir_kernel<<<G, NT, SMEM_BYTES>>>(x, out, nseq);
}

// round 7
// speedup vs baseline: 1.3782x; 1.3782x over previous
#include <cuda_runtime.h>
#include <cstdint>

// minGRU bidirectional scan. R7 = R6 design with the warp-0 shuffle deadlock
// fixed (all __shfl_up_sync at full-warp scope; only stores predicated).
// x: [B, 512, L] fp32 -> out: [B, 256, L] fp32.
//   out channel c2 (0..255): rev = c2>=128, c = c2&127
//   h row = x[b, (rev?256:0)+c, :], gate row = h row + 128 channels.
// Recurrence (logical order; rev scans t = L-1..0):
//   out_t = a_t*out_{t-1} + b_t,  a = 1/(1+e^gate), b = (1-a)*g(h),
//   g(v) = v>=0 ? 1+v : e^v.
//
// Layout: thread t owns 4 chunks of 4 logical elements, one per quarter:
//   Q_q = [q*L/4 + 4t, q*L/4 + 4t + 4)  ->  float4 index q*L/16 + t
// consecutive lanes -> consecutive 16B: perfectly coalesced LDG.128/STG.128.
// Block scan: 4 interleaved (A,B) affine scans; quarter seeds chained via
// block totals: s0 = 0, s_{q+1} = At_q * s_q + Bt_q.

constexpr int L  = 8192;
constexpr int NT = 512;
constexpr int NW = NT / 32;   // 16 warps
constexpr int QF = L / 16;    // float4s per quarter row = 512

__device__ __forceinline__ float fast_rcp(float v) {
    float r;
    asm("rcp.approx.f32 %0, %1;" : "=f"(r) : "f"(v));
    return r;
}

__global__ __launch_bounds__(NT, 2)
void mingru_bidir_kernel(const float* __restrict__ x, float* __restrict__ out) {
    __shared__ float sA[4][NW], sB[4][NW], sT[8];   // sT: totals A0..A3, B0..B3

    const int blk = blockIdx.x;
    const int b   = blk >> 8;
    const int c2  = blk & 255;
    const bool rev = (c2 & 128) != 0;
    const int hch = ((c2 & 128) ? 256 : 0) + (c2 & 127);

    const float4* __restrict__ h4 = (const float4*)(x + (size_t)(b * 512 + hch) * L);
    const float4* __restrict__ g4 = (const float4*)(x + (size_t)(b * 512 + hch + 128) * L);
    float4* __restrict__ o4 = (float4*)(out + (size_t)(b * 256 + c2) * L);

    const int tid  = threadIdx.x;
    const int lane = tid & 31;
    const int warp = tid >> 5;

    // float4 index for quarter q (same for load and store)
    int fidx[4];
    #pragma unroll
    for (int q = 0; q < 4; ++q)
        fidx[q] = rev ? (L / 4 - 1 - (q * QF + tid)) : (q * QF + tid);

    // ---- Phase 1: coalesced loads + pointwise + per-quarter chunk compose ----
    float av[16], bv[16];
    float Aq[4], Bq[4];
    #pragma unroll
    for (int q = 0; q < 4; ++q) {
        float4 hv = h4[fidx[q]];
        float4 gv = g4[fidx[q]];
        if (rev) {
            hv = make_float4(hv.w, hv.z, hv.y, hv.x);
            gv = make_float4(gv.w, gv.z, gv.y, gv.x);
        }
        const float hh[4] = {hv.x, hv.y, hv.z, hv.w};
        const float gg[4] = {gv.x, gv.y, gv.z, gv.w};
        float A = 1.0f, B = 0.0f;
        #pragma unroll
        for (int k = 0; k < 4; ++k) {
            const int j = q * 4 + k;
            const float a  = fast_rcp(1.0f + __expf(gg[k]));
            const float gh = (hh[k] >= 0.0f) ? (1.0f + hh[k]) : __expf(hh[k]);
            const float bb = (1.0f - a) * gh;
            av[j] = a;
            bv[j] = bb;
            B = fmaf(B, a, bb);
            A *= a;
        }
        Aq[q] = A;
        Bq[q] = B;
    }

    // ---- Phase 2: 4 interleaved warp scans (all shfl at full-warp scope) ----
    #pragma unroll
    for (int off = 1; off < 32; off <<= 1) {
        #pragma unroll
        for (int q = 0; q < 4; ++q) {
            const float Au = __shfl_up_sync(0xFFFFFFFFu, Aq[q], off);
            const float Bu = __shfl_up_sync(0xFFFFFFFFu, Bq[q], off);
            if (lane >= off) {
                Bq[q] = fmaf(Bu, Aq[q], Bq[q]);
                Aq[q] *= Au;
            }
        }
    }
    float Ae[4], Be[4];
    #pragma unroll
    for (int q = 0; q < 4; ++q) {
        Ae[q] = __shfl_up_sync(0xFFFFFFFFu, Aq[q], 1);
        Be[q] = __shfl_up_sync(0xFFFFFFFFu, Bq[q], 1);
        if (lane == 0) { Ae[q] = 1.0f; Be[q] = 0.0f; }
        if (lane == 31) { sA[q][warp] = Aq[q]; sB[q][warp] = Bq[q]; }
    }
    __syncthreads();

    // warp 0: block-level scan over 16 warp totals, 4 quarters interleaved.
    // ALL shuffles executed by the whole warp; only stores are predicated.
    if (warp == 0) {
        float wa[4], wb[4];
        #pragma unroll
        for (int q = 0; q < 4; ++q) {
            wa[q] = sA[q][lane & (NW - 1)];
            wb[q] = sB[q][lane & (NW - 1)];
        }
        #pragma unroll
        for (int off = 1; off < NW; off <<= 1) {
            #pragma unroll
            for (int q = 0; q < 4; ++q) {
                const float Au = __shfl_up_sync(0xFFFFFFFFu, wa[q], off);
                const float Bu = __shfl_up_sync(0xFFFFFFFFu, wb[q], off);
                if (lane >= off) {
                    wb[q] = fmaf(Bu, wa[q], wb[q]);
                    wa[q] *= Au;
                }
            }
        }
        #pragma unroll
        for (int q = 0; q < 4; ++q) {
            const float wae = __shfl_up_sync(0xFFFFFFFFu, wa[q], 1);   // full warp
            const float wbe = __shfl_up_sync(0xFFFFFFFFu, wb[q], 1);   // full warp
            if (lane < NW) {
                sA[q][lane] = (lane == 0) ? 1.0f : wae;
                sB[q][lane] = (lane == 0) ? 0.0f : wbe;
            }
            if (lane == NW - 1) { sT[q] = wa[q]; sT[4 + q] = wb[q]; }
        }
    }
    __syncthreads();

    // quarter seeds: s0 = 0, s_{q+1} = At_q * s_q + Bt_q
    float seed[4];
    seed[0] = 0.0f;
    seed[1] = sT[4];
    seed[2] = fmaf(sT[1], seed[1], sT[5]);
    seed[3] = fmaf(sT[2], seed[2], sT[6]);

    // ---- Phase 3: replay + coalesced stores ----
    #pragma unroll
    for (int q = 0; q < 4; ++q) {
        // carry entering this thread's chunk in quarter q
        float s = fmaf(Ae[q], fmaf(sA[q][warp], seed[q], sB[q][warp]), Be[q]);
        float o[4];
        #pragma unroll
        for (int k = 0; k < 4; ++k) {
            s = fmaf(av[q * 4 + k], s, bv[q * 4 + k]);
            o[k] = s;
        }
        o4[fidx[q]] = rev ? make_float4(o[3], o[2], o[1], o[0])
                          : make_float4(o[0], o[1], o[2], o[3]);
    }
}

extern "C" void kernel_launch(void* const* d_in, const int* in_sizes, int n_in,
                              void* d_out, int out_size) {
    const float* x = (const float*)d_in[0];
    float* out = (float*)d_out;
    const int B = in_sizes[0] / (512 * L);
    mingru_bidir_kernel<<<B * 256, NT>>>(x, out);
}

// round 8
// speedup vs baseline: 1.5024x; 1.0901x over previous
#include <cuda_runtime.h>
#include <cstdint>

// minGRU bidirectional scan. R8: TMA bulk load -> smem (R3's memory engine)
// + split-chunk vector LDS + R7's 4-quarter interleaved scan + direct STG out.
// x: [B, 512, L] fp32 -> out: [B, 256, L] fp32.
//   out channel c2 (0..255): rev = c2>=128, c = c2&127
//   h row = x[b, (rev?256:0)+c, :], gate row = h row + 128 channels.
// Recurrence (logical order; rev scans t = L-1..0):
//   out_t = a_t*out_{t-1} + b_t,  a = 1/(1+e^gate), b = (1-a)*g(h),
//   g(v) = v>=0 ? 1+v : e^v.
//
// Thread t owns 4 chunks of 4 logical elems, one per quarter:
//   Q_q = [q*L/4 + 4t, q*L/4 + 4t + 4)  ->  float4 index q*L/16 + t
// LDS.128: consecutive lanes -> consecutive 16B -> conflict-free.
// STG.128: same layout -> perfectly coalesced.

constexpr int L  = 8192;
constexpr int NT = 512;
constexpr int NW = NT / 32;   // 16 warps
constexpr int QF = L / 16;    // float4s per quarter = 512

// dynamic smem: hbuf[L] | gbuf[L] | mbar (16B aligned)
constexpr int SMEM_BYTES = 2 * L * 4 + 16;

__device__ __forceinline__ float fast_rcp(float v) {
    float r;
    asm("rcp.approx.f32 %0, %1;" : "=f"(r) : "f"(v));
    return r;
}

__device__ __forceinline__ void mbar_wait_parity0(uint32_t mbar) {
    uint32_t done;
    asm volatile(
        "{\n\t.reg .pred p;\n\t"
        "mbarrier.try_wait.parity.shared::cta.b64 p, [%1], 0;\n\t"
        "selp.b32 %0, 1, 0, p;\n\t}"
        : "=r"(done) : "r"(mbar) : "memory");
    while (!done) {
        asm volatile(
            "{\n\t.reg .pred p;\n\t"
            "mbarrier.try_wait.parity.shared::cta.b64 p, [%1], 0, 0x989680;\n\t"
            "selp.b32 %0, 1, 0, p;\n\t}"
            : "=r"(done) : "r"(mbar) : "memory");
    }
}

__global__ __launch_bounds__(NT, 2)
void mingru_bidir_kernel(const float* __restrict__ x, float* __restrict__ out) {
    extern __shared__ float smem[];
    float* hbuf = smem;
    float* gbuf = smem + L;
    uint64_t* mbar64 = (uint64_t*)(smem + 2 * L);

    __shared__ float sA[4][NW], sB[4][NW], sT[8];

    const int blk = blockIdx.x;
    const int b   = blk >> 8;
    const int c2  = blk & 255;
    const bool rev = (c2 & 128) != 0;
    const int hch = ((c2 & 128) ? 256 : 0) + (c2 & 127);

    const float* hrow = x + (size_t)(b * 512 + hch) * L;
    const float* grow = hrow + (size_t)128 * L;
    float4* __restrict__ o4 = (float4*)(out + (size_t)(b * 256 + c2) * L);

    const int tid  = threadIdx.x;
    const int lane = tid & 31;
    const int warp = tid >> 5;

    const uint32_t mbar_u32 = (uint32_t)__cvta_generic_to_shared(mbar64);
    const uint32_t hbuf_u32 = (uint32_t)__cvta_generic_to_shared(hbuf);
    const uint32_t gbuf_u32 = (uint32_t)__cvta_generic_to_shared(gbuf);

    // ---- TMA bulk load of both rows into smem ----
    if (tid == 0) {
        asm volatile("mbarrier.init.shared.b64 [%0], 1;" :: "r"(mbar_u32) : "memory");
        asm volatile("mbarrier.arrive.expect_tx.shared.b64 _, [%0], %1;"
                     :: "r"(mbar_u32), "r"(2 * L * 4) : "memory");
        asm volatile("cp.async.bulk.shared::cta.global.mbarrier::complete_tx::bytes "
                     "[%0], [%1], %2, [%3];"
                     :: "r"(hbuf_u32), "l"(hrow), "r"(L * 4), "r"(mbar_u32) : "memory");
        asm volatile("cp.async.bulk.shared::cta.global.mbarrier::complete_tx::bytes "
                     "[%0], [%1], %2, [%3];"
                     :: "r"(gbuf_u32), "l"(grow), "r"(L * 4), "r"(mbar_u32) : "memory");
    }
    __syncthreads();
    mbar_wait_parity0(mbar_u32);

    const float4* h4 = (const float4*)hbuf;
    const float4* g4 = (const float4*)gbuf;

    // float4 index for quarter q (load from smem, store to global — same index)
    int fidx[4];
    #pragma unroll
    for (int q = 0; q < 4; ++q)
        fidx[q] = rev ? (L / 4 - 1 - (q * QF + tid)) : (q * QF + tid);

    // ---- Phase 1: conflict-free LDS.128 + pointwise + per-quarter compose ----
    float av[16], bv[16];
    float Aq[4], Bq[4];
    #pragma unroll
    for (int q = 0; q < 4; ++q) {
        float4 hv = h4[fidx[q]];
        float4 gv = g4[fidx[q]];
        if (rev) {
            hv = make_float4(hv.w, hv.z, hv.y, hv.x);
            gv = make_float4(gv.w, gv.z, gv.y, gv.x);
        }
        const float hh[4] = {hv.x, hv.y, hv.z, hv.w};
        const float gg[4] = {gv.x, gv.y, gv.z, gv.w};
        float A = 1.0f, B = 0.0f;
        #pragma unroll
        for (int k = 0; k < 4; ++k) {
            const int j = q * 4 + k;
            const float a  = fast_rcp(1.0f + __expf(gg[k]));
            const float gh = (hh[k] >= 0.0f) ? (1.0f + hh[k]) : __expf(hh[k]);
            const float bb = (1.0f - a) * gh;
            av[j] = a;
            bv[j] = bb;
            B = fmaf(B, a, bb);
            A *= a;
        }
        Aq[q] = A;
        Bq[q] = B;
    }

    // ---- Phase 2: 4 interleaved warp scans (all shfl at full-warp scope) ----
    #pragma unroll
    for (int off = 1; off < 32; off <<= 1) {
        #pragma unroll
        for (int q = 0; q < 4; ++q) {
            const float Au = __shfl_up_sync(0xFFFFFFFFu, Aq[q], off);
            const float Bu = __shfl_up_sync(0xFFFFFFFFu, Bq[q], off);
            if (lane >= off) {
                Bq[q] = fmaf(Bu, Aq[q], Bq[q]);
                Aq[q] *= Au;
            }
        }
    }
    float Ae[4], Be[4];
    #pragma unroll
    for (int q = 0; q < 4; ++q) {
        Ae[q] = __shfl_up_sync(0xFFFFFFFFu, Aq[q], 1);
        Be[q] = __shfl_up_sync(0xFFFFFFFFu, Bq[q], 1);
        if (lane == 0) { Ae[q] = 1.0f; Be[q] = 0.0f; }
        if (lane == 31) { sA[q][warp] = Aq[q]; sB[q][warp] = Bq[q]; }
    }
    __syncthreads();

    // warp 0: block scan over 16 warp totals, 4 quarters interleaved
    if (warp == 0) {
        float wa[4], wb[4];
        #pragma unroll
        for (int q = 0; q < 4; ++q) {
            wa[q] = sA[q][lane & (NW - 1)];
            wb[q] = sB[q][lane & (NW - 1)];
        }
        #pragma unroll
        for (int off = 1; off < NW; off <<= 1) {
            #pragma unroll
            for (int q = 0; q < 4; ++q) {
                const float Au = __shfl_up_sync(0xFFFFFFFFu, wa[q], off);
                const float Bu = __shfl_up_sync(0xFFFFFFFFu, wb[q], off);
                if (lane >= off) {
                    wb[q] = fmaf(Bu, wa[q], wb[q]);
                    wa[q] *= Au;
                }
            }
        }
        #pragma unroll
        for (int q = 0; q < 4; ++q) {
            const float wae = __shfl_up_sync(0xFFFFFFFFu, wa[q], 1);   // full warp
            const float wbe = __shfl_up_sync(0xFFFFFFFFu, wb[q], 1);   // full warp
            if (lane < NW) {
                sA[q][lane] = (lane == 0) ? 1.0f : wae;
                sB[q][lane] = (lane == 0) ? 0.0f : wbe;
            }
            if (lane == NW - 1) { sT[q] = wa[q]; sT[4 + q] = wb[q]; }
        }
    }
    __syncthreads();

    // quarter seeds: s0 = 0, s_{q+1} = At_q * s_q + Bt_q
    float seed[4];
    seed[0] = 0.0f;
    seed[1] = sT[4];
    seed[2] = fmaf(sT[1], seed[1], sT[5]);
    seed[3] = fmaf(sT[2], seed[2], sT[6]);

    // ---- Phase 3: replay + direct coalesced STG.128 ----
    #pragma unroll
    for (int q = 0; q < 4; ++q) {
        float s = fmaf(Ae[q], fmaf(sA[q][warp], seed[q], sB[q][warp]), Be[q]);
        float o[4];
        #pragma unroll
        for (int k = 0; k < 4; ++k) {
            s = fmaf(av[q * 4 + k], s, bv[q * 4 + k]);
            o[k] = s;
        }
        o4[fidx[q]] = rev ? make_float4(o[3], o[2], o[1], o[0])
                          : make_float4(o[0], o[1], o[2], o[3]);
    }
}

extern "C" void kernel_launch(void* const* d_in, const int* in_sizes, int n_in,
                              void* d_out, int out_size) {
    const float* x = (const float*)d_in[0];
    float* out = (float*)d_out;
    const int B = in_sizes[0] / (512 * L);
    cudaFuncSetAttribute(mingru_bidir_kernel,
                         cudaFuncAttributeMaxDynamicSharedMemorySize, SMEM_BYTES);
    mingru_bidir_kernel<<<B * 256, NT, SMEM_BYTES>>>(x, out);
}